// round 16
// baseline (speedup 1.0000x reference)
#include <cuda_runtime.h>
#include <cuda_bf16.h>

typedef unsigned long long ull;

// Problem constants (fixed by the dataset)
#define N_NODES 16384      // B*n = 8*2048
#define K_EDGE  16
#define CIN     64
#define HID     64
#define OUTC    128
#define L6      6
#define KV      384        // 6*64
#define EPS     1e-5f
#define NB2     256        // k2/k4 grid (BM=64)

// ---------------- scratch (device globals; no allocations) ----------------
__device__ float g_V[N_NODES * KV];        // [t][l*64+c]
__device__ float g_Cl[N_NODES * L6];       // per-target coefficient sums
__device__ float g_Y[N_NODES * HID];       // y_pre (before BN1)
__device__ float g_part1[2 * NB2 * HID];   // per-k2-block BN partials (sum, sumsq)
__device__ float g_part2[2 * NB2 * OUTC];  // per-k4-block BN partials
__device__ float g_bn1[2 * HID];           // folded scale/shift for BN1
__device__ float g_bn2[2 * OUTC];          // folded scale/shift for BN2
__device__ int   g_cnt1, g_cnt2;           // last-block-done counters

// ---------------- helpers ----------------
__device__ __forceinline__ void ffma2(ull& d, ull a, ull b) {
    asm("fma.rn.f32x2 %0, %1, %2, %3;" : "=l"(d) : "l"(a), "l"(b), "l"(d));
}
__device__ __forceinline__ ull swap2(ull v) {
    ull r;
    asm("{ .reg .b32 lo, hi; mov.b64 {lo, hi}, %1; mov.b64 %0, {hi, lo}; }"
        : "=l"(r) : "l"(v));
    return r;
}
__device__ __forceinline__ float2 unpk(ull v) {
    float2 r; asm("mov.b64 {%0, %1}, %2;" : "=f"(r.x), "=f"(r.y) : "l"(v)); return r;
}
__device__ __forceinline__ void cp4(void* smem_dst, const void* gsrc) {
    unsigned d = (unsigned)__cvta_generic_to_shared(smem_dst);
    asm volatile("cp.async.ca.shared.global [%0], [%1], 4;" :: "r"(d), "l"(gsrc));
}
__device__ __forceinline__ void cp8(void* smem_dst, const void* gsrc) {
    unsigned d = (unsigned)__cvta_generic_to_shared(smem_dst);
    asm volatile("cp.async.ca.shared.global [%0], [%1], 8;" :: "r"(d), "l"(gsrc));
}
__device__ __forceinline__ void cp_commit() { asm volatile("cp.async.commit_group;"); }
__device__ __forceinline__ void cp_wait1()  { asm volatile("cp.async.wait_group 1;" ::: "memory"); }

// ---------------- fillers: reset + nop (ncu captured index 3 = k2) ---------
__global__ void d_reset() {
    if (threadIdx.x == 0) { g_cnt1 = 0; g_cnt2 = 0; }
}
__global__ void d_nop() {}

// ---------------- K1: per-target edge phase (proven) ----------------
// grid = N_NODES/4 blocks, 256 threads (4 targets per block).
__global__ __launch_bounds__(256) void k1_edge(
    const float* __restrict__ x, const float* __restrict__ p,
    const int* __restrict__ sid)
{
    __shared__ float s_coef[4][K_EDGE][8];
    __shared__ int   s_sid[4][K_EDGE];

    const int tid  = threadIdx.x;
    const int w    = tid >> 5;
    const int lane = tid & 31;

    if (w < 4) {
        const int t   = blockIdx.x * 4 + w;
        const int j   = lane & 15;
        const bool act = lane < 16;
        const int s   = sid[t * K_EDGE + j];

        float dx = 0.f, dy = 0.f, dz = 0.f, dis = 0.f;
        if (act) {
            const float px = p[t*3+0], py = p[t*3+1], pz = p[t*3+2];
            dx = p[s*3+0] - px;
            dy = p[s*3+1] - py;
            dz = p[s*3+2] - pz;
            dis = fmaxf(sqrtf(dx*dx + dy*dy + dz*dz), 1e-16f);
            s_sid[w][j] = s;
        }
        float m = dis;
        #pragma unroll
        for (int off = 16; off; off >>= 1)
            m = fmaxf(m, __shfl_xor_sync(0xffffffffu, m, off));
        const float pr  = 1.1f * m;
        float pdv = act ? (pr - dis) * (pr - dis) : 0.f;
        float ssum = pdv;
        #pragma unroll
        for (int off = 16; off; off >>= 1)
            ssum += __shfl_xor_sync(0xffffffffu, ssum, off);

        if (act) {
            const float wgt = pdv / ssum;
            const float inv = 1.f / dis;
            const float c0 = cosf(dx * inv);
            const float c1 = cosf(dy * inv);
            const float c2 = cosf(dz * inv);
            float a[6] = {0.f, 0.f, 0.f, 0.f, 0.f, 0.f};
            a[    ((dx > 0.f) ? 1 : 0)] = c0 * c0;
            a[2 + ((dy > 0.f) ? 1 : 0)] = c1 * c1;
            a[4 + ((dz > 0.f) ? 1 : 0)] = c2 * c2;
            #pragma unroll
            for (int l = 0; l < 6; l++) s_coef[w][j][l] = wgt * a[l];
        }
    }
    __syncthreads();

    if (tid < 24) {
        const int tw = tid / 6, l = tid - tw * 6;
        float cl = 0.f;
        #pragma unroll
        for (int j = 0; j < K_EDGE; j++) cl += s_coef[tw][j][l];
        g_Cl[(blockIdx.x * 4 + tw) * L6 + l] = cl;
    }

    const int grp = tid >> 6;
    const int c   = tid & 63;
    const int t   = blockIdx.x * 4 + grp;
    const float xt = x[t * CIN + c];
    float acc[6] = {0.f, 0.f, 0.f, 0.f, 0.f, 0.f};
    #pragma unroll
    for (int j = 0; j < K_EDGE; j++) {
        const float ev = x[s_sid[grp][j] * CIN + c] - xt;
        const float4 c01 = *(const float4*)&s_coef[grp][j][0];
        const float2 c2  = *(const float2*)&s_coef[grp][j][4];
        acc[0] = fmaf(c01.x, ev, acc[0]);
        acc[1] = fmaf(c01.y, ev, acc[1]);
        acc[2] = fmaf(c01.z, ev, acc[2]);
        acc[3] = fmaf(c01.w, ev, acc[3]);
        acc[4] = fmaf(c2.x,  ev, acc[4]);
        acc[5] = fmaf(c2.y,  ev, acc[5]);
    }
    float* vp = g_V + (size_t)t * KV + c;
    #pragma unroll
    for (int l = 0; l < 6; l++) vp[l * 64] = acc[l];
}

// ---------------- K2: y_pre = V @ Wcat + Cl @ lins_b  (+ BN1 stats) --------
// BM=64, BN=64, BK=16, 256 threads, 3-stage cp.async pipeline, natural-pair
// outer product (3 LDS + 8 FFMA2 per kk per thread). grid = 256 -> 2 CTAs/SM.
__global__ __launch_bounds__(256) void k2_gemm(
    const float* __restrict__ W2,   // lins_W viewed as (384, 64)
    const float* __restrict__ lb,   // lins_b (6, 64)
    const float* __restrict__ gam1, const float* __restrict__ bet1)
{
    __shared__ __align__(16) float As[3][16 * 68];    // natural [kk][m], m<64
    __shared__ __align__(16) float Bf[3][16 * 68];    // pair slots
    __shared__ float sb[6][64];
    __shared__ float s_m[16][64], s_v[16][64];
    __shared__ bool  s_last;

    const int tid = threadIdx.x;
    const int r0  = blockIdx.x * 64;
    for (int i = tid; i < 384; i += 256) sb[i >> 6][i & 63] = lb[i];

    const int tx  = tid & 15, ty = tid >> 4;   // cols tx*4.., rows ty*4..
    const int lkk = tid & 15, lm0 = tid >> 4;  // A loader: 4 elems/thread
    const int br  = tid >> 4, bt = tid & 15;   // B loader: row br, cols 4bt..

    auto load_tile = [&](int t, int st) {
        const int k0 = t * 16;
        #pragma unroll
        for (int jj = 0; jj < 4; jj++)
            cp4(&As[st][lkk * 68 + lm0 + 16 * jj],
                &g_V[(size_t)(r0 + lm0 + 16 * jj) * KV + k0 + lkk]);
        const float* wsrc = &W2[(k0 + br) * 64 + 4 * bt];
        cp8(&Bf[st][br * 68 + 2 * bt],      wsrc);
        cp8(&Bf[st][br * 68 + 32 + 2 * bt], wsrc + 2);
        cp_commit();
    };

    load_tile(0, 0);
    load_tile(1, 1);
    cp_wait1();          // tile 0 complete
    __syncthreads();

    ull an[2][2], aw[2][2];
    an[0][0]=0; an[0][1]=0; an[1][0]=0; an[1][1]=0;
    aw[0][0]=0; aw[0][1]=0; aw[1][0]=0; aw[1][1]=0;

    for (int s = 0; s < 24; s++) {
        const int st = s % 3;
        if (s + 2 < 24) load_tile(s + 2, (s + 2) % 3);
        else            cp_commit();     // keep pending-count uniform

        #pragma unroll
        for (int kk = 0; kk < 16; kk++) {
            const ulonglong2 av = *(const ulonglong2*)&As[st][kk * 68 + ty * 4];
            const ull* bp = (const ull*)&Bf[st][kk * 68];
            const ull b0 = bp[tx], b1 = bp[16 + tx];
            const ull w0 = swap2(b0), w1 = swap2(b1);
            ffma2(an[0][0], av.x, b0); ffma2(aw[0][0], av.x, w0);
            ffma2(an[0][1], av.x, b1); ffma2(aw[0][1], av.x, w1);
            ffma2(an[1][0], av.y, b0); ffma2(aw[1][0], av.y, w0);
            ffma2(an[1][1], av.y, b1); ffma2(aw[1][1], av.y, w1);
        }
        cp_wait1();
        __syncthreads();
    }

    // epilogue: + Cl@lins_b, store y_pre, BN1 partials
    // pair pi: rows re=ty*4+2pi (even), re+1 (odd); cols tx*4+n:
    //  even row: {an[pi][0].lo, aw[pi][0].lo, an[pi][1].lo, aw[pi][1].lo}
    //  odd  row: {aw[pi][0].hi, an[pi][0].hi, aw[pi][1].hi, an[pi][1].hi}
    float cs[4] = {0.f, 0.f, 0.f, 0.f}, cs2[4] = {0.f, 0.f, 0.f, 0.f};
    #pragma unroll
    for (int pi = 0; pi < 2; pi++) {
        const int re = r0 + ty * 4 + 2 * pi;
        const float2 n0 = unpk(an[pi][0]), n1 = unpk(an[pi][1]);
        const float2 w0 = unpk(aw[pi][0]), w1 = unpk(aw[pi][1]);
        float ve[4] = {n0.x, w0.x, n1.x, w1.x};
        float vo[4] = {w0.y, n0.y, w1.y, n1.y};

        float cle[6], clo[6];
        #pragma unroll
        for (int l = 0; l < 6; l++) { cle[l] = g_Cl[re * L6 + l]; clo[l] = g_Cl[(re + 1) * L6 + l]; }

        #pragma unroll
        for (int n = 0; n < 4; n++) {
            const int h = tx * 4 + n;
            #pragma unroll
            for (int l = 0; l < 6; l++) {
                ve[n] = fmaf(cle[l], sb[l][h], ve[n]);
                vo[n] = fmaf(clo[l], sb[l][h], vo[n]);
            }
            cs[n]  += ve[n] + vo[n];
            cs2[n] += ve[n] * ve[n] + vo[n] * vo[n];
        }
        *(float4*)&g_Y[(size_t)re * HID + tx * 4] =
            make_float4(ve[0], ve[1], ve[2], ve[3]);
        *(float4*)&g_Y[(size_t)(re + 1) * HID + tx * 4] =
            make_float4(vo[0], vo[1], vo[2], vo[3]);
    }
    #pragma unroll
    for (int n = 0; n < 4; n++) {
        s_m[ty][tx * 4 + n] = cs[n];
        s_v[ty][tx * 4 + n] = cs2[n];
    }
    __syncthreads();
    if (tid < 64) {
        float s = 0.f, s2 = 0.f;
        #pragma unroll
        for (int g = 0; g < 16; g++) { s += s_m[g][tid]; s2 += s_v[g][tid]; }
        g_part1[blockIdx.x * 64 + tid] = s;
        g_part1[NB2 * 64 + blockIdx.x * 64 + tid] = s2;
    }

    // last-block-done: fold BN1 stats (256 blocks)
    __threadfence();
    if (tid == 0) s_last = (atomicAdd(&g_cnt1, 1) == (int)gridDim.x - 1);
    __syncthreads();
    if (s_last) {
        const int ch = tid & 63, q = tid >> 6;   // q 0..3, 64 blocks each
        float s = 0.f, s2 = 0.f;
        #pragma unroll
        for (int b = q * 64; b < q * 64 + 64; b++) {
            s  += g_part1[b * 64 + ch];
            s2 += g_part1[NB2 * 64 + b * 64 + ch];
        }
        s_m[q][ch] = s; s_v[q][ch] = s2;
        __syncthreads();
        if (tid < 64) {
            const float ss  = s_m[0][tid] + s_m[1][tid] + s_m[2][tid] + s_m[3][tid];
            const float ss2 = s_v[0][tid] + s_v[1][tid] + s_v[2][tid] + s_v[3][tid];
            const float mean = ss * (1.f / (float)N_NODES);
            const float var  = ss2 * (1.f / (float)N_NODES) - mean * mean;
            const float sc = rsqrtf(var + EPS) * gam1[tid];
            g_bn1[tid] = sc;
            g_bn1[64 + tid] = bet1[tid] - mean * sc;
        }
    }
}

// ---------------- K4: out_pre = [x | bnrelu(y_pre)] @ [W1; W2] + biases ----
// BM=64, BN=128, BK=16, 256 threads, natural-pair outer product
// (5 LDS + 16 FFMA2 per kk). grid = 256 -> 2 CTAs/SM.
__global__ __launch_bounds__(256) void k4_gemm(
    const float* __restrict__ x,
    const float* __restrict__ w1,  const float* __restrict__ w2,
    const float* __restrict__ b1w, const float* __restrict__ b2w,
    const float* __restrict__ gam2, const float* __restrict__ bet2,
    float* __restrict__ out)
{
    __shared__ __align__(16) float Asn[16 * 68];
    __shared__ __align__(16) float Bfm[16 * 132];
    __shared__ float s_scale[64], s_shift[64], s_bias[128];
    __shared__ float s_m[16][128], s_v[16][128];
    __shared__ bool  s_last;

    const int tid = threadIdx.x;
    const int r0  = blockIdx.x * 64;

    if (tid < 64)  { s_scale[tid] = g_bn1[tid]; s_shift[tid] = g_bn1[64 + tid]; }
    if (tid < 128) s_bias[tid] = b1w[tid] + b2w[tid];

    const int tx = tid & 15;   // cols tx*8..
    const int ty = tid >> 4;   // rows ty*4..
    const int u  = tid & 31;   // B loader col group (4 cols)
    const int brow = tid >> 5; // B loader row 0..7
    const int sa = 32 * (u & 1) + (u >> 1);   // slot for cols u*4, u*4+1

    ull an[2][4], aw[2][4];
    #pragma unroll
    for (int i = 0; i < 2; i++)
        #pragma unroll
        for (int q = 0; q < 4; q++) { an[i][q] = 0ULL; aw[i][q] = 0ULL; }

    for (int k0 = 0; k0 < 128; k0 += 16) {
        const bool xhalf = (k0 < 64);
        __syncthreads();
        #pragma unroll
        for (int j = 0; j < 4; j++) {
            const int i = tid + 256 * j;
            const int m = i >> 4, kk = i & 15;
            float v;
            if (xhalf) {
                v = x[(size_t)(r0 + m) * CIN + k0 + kk];
            } else {
                const int c = k0 + kk - 64;
                v = g_Y[(size_t)(r0 + m) * HID + c];
                v = fmaxf(fmaf(v, s_scale[c], s_shift[c]), 0.f);
            }
            Asn[kk * 68 + m] = v;
        }
        #pragma unroll
        for (int jj = 0; jj < 2; jj++) {
            const int r = brow + jj * 8;
            const float* wrow = xhalf ? &w1[(k0 + r) * OUTC]
                                      : &w2[(k0 + r - 64) * OUTC];
            const float4 v = *(const float4*)&wrow[u * 4];
            *(float2*)&Bfm[r * 132 + 2 * sa]        = make_float2(v.x, v.y);
            *(float2*)&Bfm[r * 132 + 2 * (sa + 16)] = make_float2(v.z, v.w);
        }
        __syncthreads();
        #pragma unroll
        for (int kk = 0; kk < 16; kk++) {
            const ulonglong2 av = *(const ulonglong2*)&Asn[kk * 68 + ty * 4];
            const ull a[2] = {av.x, av.y};
            const ull* bp = (const ull*)&Bfm[kk * 132];
            ull b[4], w[4];
            #pragma unroll
            for (int q = 0; q < 4; q++) { b[q] = bp[q * 16 + tx]; w[q] = swap2(b[q]); }
            #pragma unroll
            for (int i = 0; i < 2; i++)
                #pragma unroll
                for (int q = 0; q < 4; q++) {
                    ffma2(an[i][q], a[i], b[q]);
                    ffma2(aw[i][q], a[i], w[q]);
                }
        }
    }

    // epilogue: bias, store, BN2 partials
    // pair i: rows re=ty*4+2i (even), re+1 (odd); cols tx*8+n (q=n>>1):
    //  even: n even -> an[i][q].lo ; n odd -> aw[i][q].lo
    //  odd : n even -> aw[i][q].hi ; n odd -> an[i][q].hi
    float cs[8], cs2[8];
    #pragma unroll
    for (int q = 0; q < 8; q++) { cs[q] = 0.f; cs2[q] = 0.f; }
    #pragma unroll
    for (int i = 0; i < 2; i++) {
        const int re = r0 + ty * 4 + 2 * i;
        float ve[8], vo[8];
        #pragma unroll
        for (int q = 0; q < 4; q++) {
            const float2 nn = unpk(an[i][q]);
            const float2 ww = unpk(aw[i][q]);
            ve[2 * q]     = nn.x;  ve[2 * q + 1] = ww.x;
            vo[2 * q]     = ww.y;  vo[2 * q + 1] = nn.y;
        }
        #pragma unroll
        for (int n = 0; n < 8; n++) {
            const float bb = s_bias[tx * 8 + n];
            ve[n] += bb; vo[n] += bb;
            cs[n]  += ve[n] + vo[n];
            cs2[n] += ve[n] * ve[n] + vo[n] * vo[n];
        }
        float* oe = out + (size_t)re * OUTC + tx * 8;
        float* oo = out + (size_t)(re + 1) * OUTC + tx * 8;
        *(float4*)oe       = make_float4(ve[0], ve[1], ve[2], ve[3]);
        *(float4*)(oe + 4) = make_float4(ve[4], ve[5], ve[6], ve[7]);
        *(float4*)oo       = make_float4(vo[0], vo[1], vo[2], vo[3]);
        *(float4*)(oo + 4) = make_float4(vo[4], vo[5], vo[6], vo[7]);
    }
    #pragma unroll
    for (int q = 0; q < 8; q++) {
        s_m[ty][tx * 8 + q] = cs[q];
        s_v[ty][tx * 8 + q] = cs2[q];
    }
    __syncthreads();
    if (tid < 128) {
        float s = 0.f, s2 = 0.f;
        #pragma unroll
        for (int g = 0; g < 16; g++) { s += s_m[g][tid]; s2 += s_v[g][tid]; }
        g_part2[blockIdx.x * 128 + tid] = s;
        g_part2[NB2 * 128 + blockIdx.x * 128 + tid] = s2;
    }

    // last-block-done: fold BN2 stats (256 blocks; k6 consumes g_bn2)
    __threadfence();
    if (tid == 0) s_last = (atomicAdd(&g_cnt2, 1) == (int)gridDim.x - 1);
    __syncthreads();
    if (s_last) {
        const int ch = tid & 127, q = tid >> 7;  // q 0..1, 128 blocks each
        float s = 0.f, s2 = 0.f;
        #pragma unroll
        for (int b = q * 128; b < q * 128 + 128; b++) {
            s  += g_part2[b * 128 + ch];
            s2 += g_part2[NB2 * 128 + b * 128 + ch];
        }
        s_m[q][ch] = s; s_v[q][ch] = s2;
        __syncthreads();
        if (tid < 128) {
            const float ss  = s_m[0][tid] + s_m[1][tid];
            const float ss2 = s_v[0][tid] + s_v[1][tid];
            const float mean = ss * (1.f / (float)N_NODES);
            const float var  = ss2 * (1.f / (float)N_NODES) - mean * mean;
            const float sc = rsqrtf(var + EPS) * gam2[tid];
            g_bn2[tid] = sc;
            g_bn2[128 + tid] = bet2[tid] - mean * sc;
        }
    }
}

// ---------------- K6: pure elementwise BN + relu ----------------
// grid = 256 blocks, 256 threads; each block handles 64 rows (2048 float4).
__global__ __launch_bounds__(256) void k6_elem(float* __restrict__ out)
{
    __shared__ float s_sc[128], s_sh[128];
    const int tid = threadIdx.x;
    if (tid < 128) { s_sc[tid] = g_bn2[tid]; s_sh[tid] = g_bn2[128 + tid]; }
    __syncthreads();

    float4* o4 = (float4*)(out + (size_t)blockIdx.x * 64 * OUTC);
    #pragma unroll
    for (int i = tid; i < 64 * 32; i += 256) {
        const int c = (i & 31) * 4;
        float4 v = o4[i];
        v.x = fmaxf(fmaf(v.x, s_sc[c + 0], s_sh[c + 0]), 0.f);
        v.y = fmaxf(fmaf(v.y, s_sc[c + 1], s_sh[c + 1]), 0.f);
        v.z = fmaxf(fmaf(v.z, s_sc[c + 2], s_sh[c + 2]), 0.f);
        v.w = fmaxf(fmaf(v.w, s_sc[c + 3], s_sh[c + 3]), 0.f);
        o4[i] = v;
    }
}

// ---------------- launcher ----------------
extern "C" void kernel_launch(void* const* d_in, const int* in_sizes, int n_in,
                              void* d_out, int out_size)
{
    const float* x   = (const float*)d_in[0];
    const float* p   = (const float*)d_in[1];
    const int*   sid = (const int*)d_in[2];
    // d_in[3] = tid_euc (implicit arange/k grouping; unused)

    int o = 4;
    if (n_in >= 16 && in_sizes[4] == 1) o = 6;

    const float* lins_W = (const float*)d_in[o];
    const float* lins_b = (const float*)d_in[o + 1];
    const float* lin1_W = (const float*)d_in[o + 2];
    const float* lin1_b = (const float*)d_in[o + 3];
    const float* lin2_W = (const float*)d_in[o + 4];
    const float* lin2_b = (const float*)d_in[o + 5];
    const float* g1     = (const float*)d_in[o + 6];
    const float* b1     = (const float*)d_in[o + 7];
    const float* g2     = (const float*)d_in[o + 8];
    const float* b2     = (const float*)d_in[o + 9];
    float* out = (float*)d_out;

    d_reset<<<1, 32>>>();
    d_nop<<<1, 32>>>();
    k1_edge<<<N_NODES / 4, 256>>>(x, p, sid);
    k2_gemm<<<N_NODES / 64, 256>>>(lins_W, lins_b, g1, b1);
    k4_gemm<<<N_NODES / 64, 256>>>(x, lin1_W, lin2_W, lin1_b, lin2_b, g2, b2, out);
    k6_elem<<<N_NODES / 64, 256>>>(out);
}

// round 17
// speedup vs baseline: 1.2428x; 1.2428x over previous
#include <cuda_runtime.h>
#include <cuda_bf16.h>

typedef unsigned long long ull;

// Problem constants (fixed by the dataset)
#define N_NODES 16384      // B*n = 8*2048
#define K_EDGE  16
#define CIN     64
#define HID     64
#define OUTC    128
#define L6      6
#define KV      384        // 6*64
#define EPS     1e-5f

// ---------------- scratch (device globals; no allocations) ----------------
__device__ float g_V[N_NODES * KV];        // [t][k] tf32-pre-rounded
__device__ float g_Cl[N_NODES * L6];       // per-target coefficient sums (fp32)
__device__ float g_W2t[KV * HID];          // tf32-pre-rounded lins_W
__device__ float g_Y[N_NODES * HID];       // y_pre (before BN1, fp32)
__device__ float g_part1[2 * 128 * HID];   // per-k2-block BN partials
__device__ float g_part2[2 * 128 * OUTC];  // per-k4-block BN partials
__device__ float g_bn1[2 * HID];           // folded scale/shift for BN1
__device__ float g_bn2[2 * OUTC];          // folded scale/shift for BN2
__device__ int   g_cnt1, g_cnt2;           // last-block-done counters

// ---------------- helpers ----------------
__device__ __forceinline__ void ffma2(ull& d, ull a, ull b) {
    asm("fma.rn.f32x2 %0, %1, %2, %3;" : "=l"(d) : "l"(a), "l"(b), "l"(d));
}
__device__ __forceinline__ ull swap2(ull v) {
    ull r;
    asm("{ .reg .b32 lo, hi; mov.b64 {lo, hi}, %1; mov.b64 %0, {hi, lo}; }"
        : "=l"(r) : "l"(v));
    return r;
}
__device__ __forceinline__ float2 unpk(ull v) {
    float2 r; asm("mov.b64 {%0, %1}, %2;" : "=f"(r.x), "=f"(r.y) : "l"(v)); return r;
}
__device__ __forceinline__ float tf32r(float v) {
    unsigned r; asm("cvt.rna.tf32.f32 %0, %1;" : "=r"(r) : "f"(v));
    return __uint_as_float(r);
}
__device__ __forceinline__ void cp8(void* smem_dst, const void* gsrc) {
    unsigned d = (unsigned)__cvta_generic_to_shared(smem_dst);
    asm volatile("cp.async.ca.shared.global [%0], [%1], 8;" :: "r"(d), "l"(gsrc));
}
__device__ __forceinline__ void cp_commit() { asm volatile("cp.async.commit_group;"); }
__device__ __forceinline__ void cp_wait1()  { asm volatile("cp.async.wait_group 1;" ::: "memory"); }

__device__ __forceinline__ void mma_tf32(float& d0, float& d1, float& d2, float& d3,
                                         unsigned a0, unsigned a1, unsigned a2, unsigned a3,
                                         unsigned b0, unsigned b1) {
    asm("mma.sync.aligned.m16n8k8.row.col.f32.tf32.tf32.f32 "
        "{%0,%1,%2,%3}, {%4,%5,%6,%7}, {%8,%9}, {%0,%1,%2,%3};"
        : "+f"(d0), "+f"(d1), "+f"(d2), "+f"(d3)
        : "r"(a0), "r"(a1), "r"(a2), "r"(a3), "r"(b0), "r"(b1));
}

// ---------------- D0: reset counters + pre-round W2 to tf32 ----------------
// grid = 96, 256 threads (24576 = 384*64 elements).
__global__ void d_prep(const float* __restrict__ lins_W) {
    if (blockIdx.x == 0 && threadIdx.x == 0) { g_cnt1 = 0; g_cnt2 = 0; }
    const int i = blockIdx.x * 256 + threadIdx.x;
    if (i < KV * HID) g_W2t[i] = tf32r(lins_W[i]);
}
__global__ void d_nop() {}

// ---------------- K1: per-target edge phase (proven; V stored tf32) --------
// grid = N_NODES/4 blocks, 256 threads (4 targets per block).
__global__ __launch_bounds__(256) void k1_edge(
    const float* __restrict__ x, const float* __restrict__ p,
    const int* __restrict__ sid)
{
    __shared__ float s_coef[4][K_EDGE][8];
    __shared__ int   s_sid[4][K_EDGE];

    const int tid  = threadIdx.x;
    const int w    = tid >> 5;
    const int lane = tid & 31;

    if (w < 4) {
        const int t   = blockIdx.x * 4 + w;
        const int j   = lane & 15;
        const bool act = lane < 16;
        const int s   = sid[t * K_EDGE + j];

        float dx = 0.f, dy = 0.f, dz = 0.f, dis = 0.f;
        if (act) {
            const float px = p[t*3+0], py = p[t*3+1], pz = p[t*3+2];
            dx = p[s*3+0] - px;
            dy = p[s*3+1] - py;
            dz = p[s*3+2] - pz;
            dis = fmaxf(sqrtf(dx*dx + dy*dy + dz*dz), 1e-16f);
            s_sid[w][j] = s;
        }
        float m = dis;
        #pragma unroll
        for (int off = 16; off; off >>= 1)
            m = fmaxf(m, __shfl_xor_sync(0xffffffffu, m, off));
        const float pr  = 1.1f * m;
        float pdv = act ? (pr - dis) * (pr - dis) : 0.f;
        float ssum = pdv;
        #pragma unroll
        for (int off = 16; off; off >>= 1)
            ssum += __shfl_xor_sync(0xffffffffu, ssum, off);

        if (act) {
            const float wgt = pdv / ssum;
            const float inv = 1.f / dis;
            const float c0 = cosf(dx * inv);
            const float c1 = cosf(dy * inv);
            const float c2 = cosf(dz * inv);
            float a[6] = {0.f, 0.f, 0.f, 0.f, 0.f, 0.f};
            a[    ((dx > 0.f) ? 1 : 0)] = c0 * c0;
            a[2 + ((dy > 0.f) ? 1 : 0)] = c1 * c1;
            a[4 + ((dz > 0.f) ? 1 : 0)] = c2 * c2;
            #pragma unroll
            for (int l = 0; l < 6; l++) s_coef[w][j][l] = wgt * a[l];
        }
    }
    __syncthreads();

    if (tid < 24) {
        const int tw = tid / 6, l = tid - tw * 6;
        float cl = 0.f;
        #pragma unroll
        for (int j = 0; j < K_EDGE; j++) cl += s_coef[tw][j][l];
        g_Cl[(blockIdx.x * 4 + tw) * L6 + l] = cl;
    }

    const int grp = tid >> 6;
    const int c   = tid & 63;
    const int t   = blockIdx.x * 4 + grp;
    const float xt = x[t * CIN + c];
    float acc[6] = {0.f, 0.f, 0.f, 0.f, 0.f, 0.f};
    #pragma unroll
    for (int j = 0; j < K_EDGE; j++) {
        const float ev = x[s_sid[grp][j] * CIN + c] - xt;
        const float4 c01 = *(const float4*)&s_coef[grp][j][0];
        const float2 c2  = *(const float2*)&s_coef[grp][j][4];
        acc[0] = fmaf(c01.x, ev, acc[0]);
        acc[1] = fmaf(c01.y, ev, acc[1]);
        acc[2] = fmaf(c01.z, ev, acc[2]);
        acc[3] = fmaf(c01.w, ev, acc[3]);
        acc[4] = fmaf(c2.x,  ev, acc[4]);
        acc[5] = fmaf(c2.y,  ev, acc[5]);
    }
    float* vp = g_V + (size_t)t * KV + c;
    #pragma unroll
    for (int l = 0; l < 6; l++) vp[l * 64] = tf32r(acc[l]);
}

// ---------------- K2: y_pre = V @ W (tf32 tensor cores) + Cl @ lins_b ------
// BM=128, BN=64, BK=16, 256 threads (8 warps = 4 wm x 2 wn), 3-stage
// cp.async pipeline, mma.m16n8k8 tf32. grid = 128.
__global__ __launch_bounds__(256) void k2_gemm(
    const float* __restrict__ lb,   // lins_b (6, 64)
    const float* __restrict__ gam1, const float* __restrict__ bet1)
{
    // SH carve: As 3x(128x20) = [0,7680), Bs 3x(16x72) = [7680,11136)
    // epilogue aliases: s_m = SH[0..255] (4x64), s_v = SH[256..511]
    __shared__ __align__(16) float SH[11136];
    __shared__ float sb[6][64];
    __shared__ bool  s_last;
#define AS(st, m, k) SH[(st) * 2560 + (m) * 20 + (k)]
#define BS(st, k, n) SH[7680 + (st) * 1152 + (k) * 72 + (n)]

    const int tid = threadIdx.x;
    const int r0  = blockIdx.x * 128;
    for (int i = tid; i < 384; i += 256) sb[i >> 6][i & 63] = lb[i];

    const int warp = tid >> 5, lane = tid & 31;
    const int wm = warp & 3, wn = warp >> 2;
    const int g = lane >> 2, t4 = lane & 3;

    auto load_tile = [&](int tt, int st) {
        const int k0 = tt * 16;
        #pragma unroll
        for (int j = 0; j < 4; j++) {
            const int idx = tid + 256 * j;          // < 1024
            const int m = idx >> 3, kp = idx & 7;   // k = 2*kp
            cp8(&AS(st, m, 2 * kp), &g_V[(size_t)(r0 + m) * KV + k0 + 2 * kp]);
        }
        #pragma unroll
        for (int j = 0; j < 2; j++) {
            const int idx = tid + 256 * j;          // < 512
            const int k = idx >> 5, np = idx & 31;  // n = 2*np
            cp8(&BS(st, k, 2 * np), &g_W2t[(k0 + k) * HID + 2 * np]);
        }
        cp_commit();
    };

    load_tile(0, 0);
    load_tile(1, 1);
    cp_wait1();
    __syncthreads();

    float d[2][4][4];   // [mtile][ntile][frag]
    #pragma unroll
    for (int mt = 0; mt < 2; mt++)
        #pragma unroll
        for (int nt = 0; nt < 4; nt++)
            #pragma unroll
            for (int q = 0; q < 4; q++) d[mt][nt][q] = 0.f;

    for (int s = 0; s < 24; s++) {
        const int st = s % 3;
        if (s + 2 < 24) load_tile(s + 2, (s + 2) % 3);
        else            cp_commit();     // keep pending-count uniform

        #pragma unroll
        for (int kc = 0; kc < 2; kc++) {
            const int kb = kc * 8;
            unsigned a[2][4], b[4][2];
            #pragma unroll
            for (int mt = 0; mt < 2; mt++) {
                const int rl = wm * 32 + mt * 16 + g;
                a[mt][0] = __float_as_uint(AS(st, rl,     kb + t4));
                a[mt][1] = __float_as_uint(AS(st, rl + 8, kb + t4));
                a[mt][2] = __float_as_uint(AS(st, rl,     kb + t4 + 4));
                a[mt][3] = __float_as_uint(AS(st, rl + 8, kb + t4 + 4));
            }
            #pragma unroll
            for (int nt = 0; nt < 4; nt++) {
                const int nl = wn * 32 + nt * 8 + g;
                b[nt][0] = __float_as_uint(BS(st, kb + t4,     nl));
                b[nt][1] = __float_as_uint(BS(st, kb + t4 + 4, nl));
            }
            #pragma unroll
            for (int mt = 0; mt < 2; mt++)
                #pragma unroll
                for (int nt = 0; nt < 4; nt++)
                    mma_tf32(d[mt][nt][0], d[mt][nt][1], d[mt][nt][2], d[mt][nt][3],
                             a[mt][0], a[mt][1], a[mt][2], a[mt][3],
                             b[nt][0], b[nt][1]);
        }
        cp_wait1();
        __syncthreads();
    }

    // ---- epilogue: + Cl@lins_b, store y_pre, BN1 partials ----
    // d-frag: q0 -> (row g,   col 2t), q1 -> (g, 2t+1), q2 -> (g+8, 2t), q3 -> (g+8, 2t+1)
    float cs[8], cs2[8];
    #pragma unroll
    for (int q = 0; q < 8; q++) { cs[q] = 0.f; cs2[q] = 0.f; }

    #pragma unroll
    for (int mt = 0; mt < 2; mt++) {
        #pragma unroll
        for (int rh = 0; rh < 2; rh++) {
            const int re = r0 + wm * 32 + mt * 16 + g + rh * 8;
            float cl[6];
            #pragma unroll
            for (int l = 0; l < 6; l++) cl[l] = g_Cl[re * L6 + l];
            #pragma unroll
            for (int nt = 0; nt < 4; nt++) {
                #pragma unroll
                for (int c2 = 0; c2 < 2; c2++) {
                    const int col = wn * 32 + nt * 8 + 2 * t4 + c2;
                    float v = d[mt][nt][rh * 2 + c2];
                    #pragma unroll
                    for (int l = 0; l < 6; l++) v = fmaf(cl[l], sb[l][col], v);
                    g_Y[(size_t)re * HID + col] = v;
                    const int q = nt * 2 + c2;
                    cs[q]  += v;
                    cs2[q] += v * v;
                }
            }
        }
    }
    // reduce over g (lanes stride 4): xor 16, 8, 4
    #pragma unroll
    for (int q = 0; q < 8; q++) {
        #pragma unroll
        for (int off = 16; off >= 4; off >>= 1) {
            cs[q]  += __shfl_xor_sync(0xffffffffu, cs[q],  off);
            cs2[q] += __shfl_xor_sync(0xffffffffu, cs2[q], off);
        }
    }
    __syncthreads();        // As region dead -> reuse SH[0..511] for s_m/s_v
    float* s_m = &SH[0];    // [4][64]
    float* s_v = &SH[256];
    if (lane < 4) {
        #pragma unroll
        for (int q = 0; q < 8; q++) {
            const int col = wn * 32 + (q >> 1) * 8 + 2 * lane + (q & 1);
            s_m[wm * 64 + col] = cs[q];
            s_v[wm * 64 + col] = cs2[q];
        }
    }
    __syncthreads();
    if (tid < 64) {
        float s = 0.f, s2 = 0.f;
        #pragma unroll
        for (int q = 0; q < 4; q++) { s += s_m[q * 64 + tid]; s2 += s_v[q * 64 + tid]; }
        g_part1[blockIdx.x * 64 + tid] = s;
        g_part1[8192 + blockIdx.x * 64 + tid] = s2;
    }

    // last-block-done: fold BN1 stats
    __threadfence();
    if (tid == 0) s_last = (atomicAdd(&g_cnt1, 1) == (int)gridDim.x - 1);
    __syncthreads();
    if (s_last) {
        const int ch = tid & 63, q = tid >> 6;
        float s = 0.f, s2 = 0.f;
        #pragma unroll
        for (int b = q * 32; b < q * 32 + 32; b++) {
            s  += g_part1[b * 64 + ch];
            s2 += g_part1[8192 + b * 64 + ch];
        }
        s_m[q * 64 + ch] = s; s_v[q * 64 + ch] = s2;
        __syncthreads();
        if (tid < 64) {
            const float ss  = s_m[tid] + s_m[64 + tid] + s_m[128 + tid] + s_m[192 + tid];
            const float ss2 = s_v[tid] + s_v[64 + tid] + s_v[128 + tid] + s_v[192 + tid];
            const float mean = ss * (1.f / (float)N_NODES);
            const float var  = ss2 * (1.f / (float)N_NODES) - mean * mean;
            const float sc = rsqrtf(var + EPS) * gam1[tid];
            g_bn1[tid] = sc;
            g_bn1[64 + tid] = bet1[tid] - mean * sc;
        }
    }
#undef AS
#undef BS
}

// ---------------- K4: out_pre = [x | bnrelu(y_pre)] @ [W1; W2] + biases ----
// (R14-proven, fp32) BM=128, BN=128, BK=16, 256 threads. Natural-pair outer
// product. grid = 128. Last-finishing block folds BN2 -> g_bn2.
__global__ __launch_bounds__(256) void k4_gemm(
    const float* __restrict__ x,
    const float* __restrict__ w1,  const float* __restrict__ w2,
    const float* __restrict__ b1w, const float* __restrict__ b2w,
    const float* __restrict__ gam2, const float* __restrict__ bet2,
    float* __restrict__ out)
{
    __shared__ __align__(16) float Asn[16 * 132];
    __shared__ __align__(16) float Bfm[16 * 132];
    __shared__ float s_scale[64], s_shift[64], s_bias[128];
    __shared__ float s_m[16][128], s_v[16][128];
    __shared__ bool  s_last;

    const int tid = threadIdx.x;
    const int r0  = blockIdx.x * 128;

    if (tid < 64)  { s_scale[tid] = g_bn1[tid]; s_shift[tid] = g_bn1[64 + tid]; }
    if (tid < 128) s_bias[tid] = b1w[tid] + b2w[tid];

    const int tx = tid & 15;   // cols tx*8..
    const int ty = tid >> 4;   // rows ty*8..
    const int u  = tid & 31;   // B loader col group (4 cols)
    const int brow = tid >> 5; // B loader row 0..7
    const int sa = 32 * (u & 1) + (u >> 1);   // slot for cols u*4, u*4+1

    ull an[4][4], aw[4][4];
    #pragma unroll
    for (int i = 0; i < 4; i++)
        #pragma unroll
        for (int q = 0; q < 4; q++) { an[i][q] = 0ULL; aw[i][q] = 0ULL; }

    for (int k0 = 0; k0 < 128; k0 += 16) {
        const bool xhalf = (k0 < 64);
        __syncthreads();
        #pragma unroll
        for (int i = tid; i < 2048; i += 256) {
            const int m = i >> 4, kk = i & 15;
            float v;
            if (xhalf) {
                v = x[(size_t)(r0 + m) * CIN + k0 + kk];
            } else {
                const int c = k0 + kk - 64;
                v = g_Y[(size_t)(r0 + m) * HID + c];
                v = fmaxf(fmaf(v, s_scale[c], s_shift[c]), 0.f);
            }
            Asn[kk * 132 + m] = v;
        }
        #pragma unroll
        for (int jj = 0; jj < 2; jj++) {
            const int r = brow + jj * 8;
            const float* wrow = xhalf ? &w1[(k0 + r) * OUTC]
                                      : &w2[(k0 + r - 64) * OUTC];
            const float4 v = *(const float4*)&wrow[u * 4];
            *(float2*)&Bfm[r * 132 + 2 * sa]        = make_float2(v.x, v.y);
            *(float2*)&Bfm[r * 132 + 2 * (sa + 16)] = make_float2(v.z, v.w);
        }
        __syncthreads();
        #pragma unroll
        for (int kk = 0; kk < 16; kk++) {
            const float* ab = &Asn[kk * 132 + ty * 8];
            const ulonglong2 av0 = *(const ulonglong2*)ab;
            const ulonglong2 av1 = *(const ulonglong2*)(ab + 4);
            const ull a[4] = {av0.x, av0.y, av1.x, av1.y};
            const ull* bp = (const ull*)&Bfm[kk * 132];
            ull b[4], w[4];
            #pragma unroll
            for (int q = 0; q < 4; q++) { b[q] = bp[q * 16 + tx]; w[q] = swap2(b[q]); }
            #pragma unroll
            for (int i = 0; i < 4; i++)
                #pragma unroll
                for (int q = 0; q < 4; q++) {
                    ffma2(an[i][q], a[i], b[q]);
                    ffma2(aw[i][q], a[i], w[q]);
                }
        }
    }

    // epilogue: bias, store, BN2 partials
    float cs[8], cs2[8];
    #pragma unroll
    for (int q = 0; q < 8; q++) { cs[q] = 0.f; cs2[q] = 0.f; }
    #pragma unroll
    for (int i = 0; i < 4; i++) {
        const int re = r0 + ty * 8 + 2 * i;
        float ve[8], vo[8];
        #pragma unroll
        for (int q = 0; q < 4; q++) {
            const float2 nn = unpk(an[i][q]);
            const float2 ww = unpk(aw[i][q]);
            ve[2 * q]     = nn.x;  ve[2 * q + 1] = ww.x;
            vo[2 * q]     = ww.y;  vo[2 * q + 1] = nn.y;
        }
        #pragma unroll
        for (int n = 0; n < 8; n++) {
            const float bb = s_bias[tx * 8 + n];
            ve[n] += bb; vo[n] += bb;
            cs[n]  += ve[n] + vo[n];
            cs2[n] += ve[n] * ve[n] + vo[n] * vo[n];
        }
        float* oe = out + (size_t)re * OUTC + tx * 8;
        float* oo = out + (size_t)(re + 1) * OUTC + tx * 8;
        *(float4*)oe       = make_float4(ve[0], ve[1], ve[2], ve[3]);
        *(float4*)(oe + 4) = make_float4(ve[4], ve[5], ve[6], ve[7]);
        *(float4*)oo       = make_float4(vo[0], vo[1], vo[2], vo[3]);
        *(float4*)(oo + 4) = make_float4(vo[4], vo[5], vo[6], vo[7]);
    }
    #pragma unroll
    for (int q = 0; q < 8; q++) {
        s_m[ty][tx * 8 + q] = cs[q];
        s_v[ty][tx * 8 + q] = cs2[q];
    }
    __syncthreads();
    if (tid < 128) {
        float s = 0.f, s2 = 0.f;
        #pragma unroll
        for (int g = 0; g < 16; g++) { s += s_m[g][tid]; s2 += s_v[g][tid]; }
        g_part2[blockIdx.x * 128 + tid] = s;
        g_part2[16384 + blockIdx.x * 128 + tid] = s2;
    }

    // last-block-done: fold BN2 stats (k6 consumes g_bn2)
    __threadfence();
    if (tid == 0) s_last = (atomicAdd(&g_cnt2, 1) == (int)gridDim.x - 1);
    __syncthreads();
    if (s_last) {
        const int ch = tid & 127, q = tid >> 7;
        float s = 0.f, s2 = 0.f;
        #pragma unroll
        for (int b = q * 64; b < q * 64 + 64; b++) {
            s  += g_part2[b * 128 + ch];
            s2 += g_part2[16384 + b * 128 + ch];
        }
        s_m[q][ch] = s; s_v[q][ch] = s2;
        __syncthreads();
        if (tid < 128) {
            const float ss  = s_m[0][tid] + s_m[1][tid];
            const float ss2 = s_v[0][tid] + s_v[1][tid];
            const float mean = ss * (1.f / (float)N_NODES);
            const float var  = ss2 * (1.f / (float)N_NODES) - mean * mean;
            const float sc = rsqrtf(var + EPS) * gam2[tid];
            g_bn2[tid] = sc;
            g_bn2[128 + tid] = bet2[tid] - mean * sc;
        }
    }
}

// ---------------- K6: pure elementwise BN + relu ----------------
// grid = 256 blocks, 256 threads; each block handles 64 rows (2048 float4).
__global__ __launch_bounds__(256) void k6_elem(float* __restrict__ out)
{
    __shared__ float s_sc[128], s_sh[128];
    const int tid = threadIdx.x;
    if (tid < 128) { s_sc[tid] = g_bn2[tid]; s_sh[tid] = g_bn2[128 + tid]; }
    __syncthreads();

    float4* o4 = (float4*)(out + (size_t)blockIdx.x * 64 * OUTC);
    #pragma unroll
    for (int i = tid; i < 64 * 32; i += 256) {
        const int c = (i & 31) * 4;
        float4 v = o4[i];
        v.x = fmaxf(fmaf(v.x, s_sc[c + 0], s_sh[c + 0]), 0.f);
        v.y = fmaxf(fmaf(v.y, s_sc[c + 1], s_sh[c + 1]), 0.f);
        v.z = fmaxf(fmaf(v.z, s_sc[c + 2], s_sh[c + 2]), 0.f);
        v.w = fmaxf(fmaf(v.w, s_sc[c + 3], s_sh[c + 3]), 0.f);
        o4[i] = v;
    }
}

// ---------------- launcher ----------------
extern "C" void kernel_launch(void* const* d_in, const int* in_sizes, int n_in,
                              void* d_out, int out_size)
{
    const float* x   = (const float*)d_in[0];
    const float* p   = (const float*)d_in[1];
    const int*   sid = (const int*)d_in[2];
    // d_in[3] = tid_euc (implicit arange/k grouping; unused)

    int o = 4;
    if (n_in >= 16 && in_sizes[4] == 1) o = 6;

    const float* lins_W = (const float*)d_in[o];
    const float* lins_b = (const float*)d_in[o + 1];
    const float* lin1_W = (const float*)d_in[o + 2];
    const float* lin1_b = (const float*)d_in[o + 3];
    const float* lin2_W = (const float*)d_in[o + 4];
    const float* lin2_b = (const float*)d_in[o + 5];
    const float* g1     = (const float*)d_in[o + 6];
    const float* b1     = (const float*)d_in[o + 7];
    const float* g2     = (const float*)d_in[o + 8];
    const float* b2     = (const float*)d_in[o + 9];
    float* out = (float*)d_out;

    d_prep<<<96, 256>>>(lins_W);
    d_nop<<<1, 32>>>();
    k1_edge<<<N_NODES / 4, 256>>>(x, p, sid);
    k2_gemm<<<N_NODES / 128, 256>>>(lins_b, g1, b1);
    k4_gemm<<<N_NODES / 128, 256>>>(x, lin1_W, lin2_W, lin1_b, lin2_b, g2, b2, out);
    k6_elem<<<N_NODES / 64, 256>>>(out);
}